// round 14
// baseline (speedup 1.0000x reference)
#include <cuda_runtime.h>
#include <cstdint>
#include <cstddef>

namespace {

constexpr int PAD_ID  = 72;     // VOCAB
constexpr int NB_MAIN = 592;    // 4 CTAs/SM * 148 SMs — exactly one wave
constexpr int CTX_J   = 4;      // ctx tokens per Wt pass
constexpr int ACT_J   = 8;      // action tokens per tail pass
constexpr int LSIZE   = 232;    // >= max tokens one CTA can own (8 warps * 28)

// ctx_W transposed: g_Wt[k][d] = ctx_W[d][k]  (143 x 256 = 146 KB)
__device__ float g_Wt[143 * 256];

// warp LayerNorm stats over 256 values (8 per lane)
__device__ __forceinline__ void warp_ln(const float* h, float& mu, float& rs)
{
    float s1 = 0.f, s2 = 0.f;
#pragma unroll
    for (int k = 0; k < 8; ++k) { s1 += h[k]; s2 = fmaf(h[k], h[k], s2); }
#pragma unroll
    for (int o = 16; o; o >>= 1) {
        s1 += __shfl_xor_sync(0xffffffffu, s1, o);
        s2 += __shfl_xor_sync(0xffffffffu, s2, o);
    }
    mu = s1 * (1.f / 256.f);
    float var = s2 * (1.f / 256.f) - mu * mu;
    rs = rsqrtf(var + 1e-5f);
}

// ============ single fused kernel: gathers in loop; action + ctx MLPs in CTA tails ============
__global__ __launch_bounds__(256, 4) void poker_fused_kernel(
    const int*   __restrict__ token_ids,
    const int*   __restrict__ token_streets,
    const int*   __restrict__ card_ranks,
    const int*   __restrict__ card_suits,
    const int*   __restrict__ action_actors,
    const float* __restrict__ legal_masks,   // [T,16]
    const float* __restrict__ cf,            // [T,9]
    const float* __restrict__ base_emb,      // [73,256]
    const float* __restrict__ street_emb,    // [4,256]
    const float* __restrict__ rank_emb,      // [13,256]
    const float* __restrict__ suit_emb,      // [4,256]
    const float* __restrict__ actor_emb,     // [2,256]
    const float* __restrict__ atype_emb,     // [16,256]
    const float* __restrict__ legal_W,       // [256,16]
    const float* __restrict__ legal_b,
    const float* __restrict__ legal_g,
    const float* __restrict__ legal_be,
    const float* __restrict__ game_W,        // [256,5]
    const float* __restrict__ game_b,
    const float* __restrict__ game_g,
    const float* __restrict__ game_be,
    const float* __restrict__ ctx_W,         // [256,143] (transposed into g_Wt)
    const float* __restrict__ ctx_b,
    const float* __restrict__ ctx_g,
    const float* __restrict__ ctx_be,
    float*       __restrict__ out,           // [T,256]
    int tokens)
{
    __shared__ int    s_alist[LSIZE];
    __shared__ int    s_clist[LSIZE];
    __shared__ int    s_acnt, s_ccnt;
    __shared__ float  s_x[ACT_J][16];
    __shared__ float  s_ca[CTX_J][144];
    __shared__ float  s_red[8][ACT_J][2];
    __shared__ float  s_ms[ACT_J][2];

    const int tid  = threadIdx.x;
    const int lane = tid & 31;
    const int wid  = tid >> 5;

    // ---- fold the ctx_W transpose into the first 143 blocks.
    // Safe: grid is exactly one co-resident wave (launch_bounds-guaranteed); writes
    // finish in ~2k cycles; first g_Wt read is after each CTA's full main loop.
    if (blockIdx.x < 143) {
        const int k = blockIdx.x;
        g_Wt[k * 256 + tid] = __ldg(ctx_W + tid * 143 + k);
    }

    if (tid == 0) { s_acnt = 0; s_ccnt = 0; }
    __syncthreads();

    const int gwarp = blockIdx.x * 8 + wid;
    const int nwarp = gridDim.x * 8;
    const int l8    = lane << 3;
    const int lq    = lane * 2;

    // software pipeline: ids AND base_emb gather issued one iteration ahead
    int t   = gwarp;
    int raw = 0, st = 0;
    float4 b0 = make_float4(0.f,0.f,0.f,0.f), b1 = b0;
    if (t < tokens) {
        raw = __ldg(token_ids + t);
        st  = __ldg(token_streets + t);
        const int id0 = raw < 0 ? PAD_ID : raw;
        const float4* bp = reinterpret_cast<const float4*>(base_emb) + id0 * 64 + lq;
        b0 = __ldg(bp); b1 = __ldg(bp + 1);
    }

    while (t < tokens) {
        const int tn = t + nwarp;
        int raw_n = 0, st_n = 0;
        float4 b0n = make_float4(0.f,0.f,0.f,0.f), b1n = b0n;
        if (tn < tokens) {
            raw_n = __ldg(token_ids + tn);
            st_n  = __ldg(token_streets + tn);
            const int idn = raw_n < 0 ? PAD_ID : raw_n;
            const float4* bpn = reinterpret_cast<const float4*>(base_emb) + idn * 64 + lq;
            b0n = __ldg(bpn); b1n = __ldg(bpn + 1);
        }

        const bool pad = raw < 0;
        const int  id  = pad ? PAD_ID : raw;

        float ar[8];
        {
            const float4* sp = reinterpret_cast<const float4*>(street_emb) + st * 64 + lq;
            const float4 s0 = __ldg(sp), s1 = __ldg(sp + 1);
            ar[0] = b0.x + s0.x; ar[1] = b0.y + s0.y; ar[2] = b0.z + s0.z; ar[3] = b0.w + s0.w;
            ar[4] = b1.x + s1.x; ar[5] = b1.y + s1.y; ar[6] = b1.z + s1.z; ar[7] = b1.w + s1.w;
        }

        if (id >= 4 && id < 56) {
            // ---- card token ----
            int rk = __ldg(card_ranks + t); rk = rk < 0 ? 0 : (rk > 12 ? 12 : rk);
            int su = __ldg(card_suits + t); su = su < 0 ? 0 : (su > 3  ? 3  : su);
            const float4* rp = reinterpret_cast<const float4*>(rank_emb) + rk * 64 + lq;
            const float4* up = reinterpret_cast<const float4*>(suit_emb) + su * 64 + lq;
            const float4 r0 = __ldg(rp), r1 = __ldg(rp + 1);
            const float4 u0 = __ldg(up), u1 = __ldg(up + 1);
            ar[0] += r0.x + u0.x; ar[1] += r0.y + u0.y; ar[2] += r0.z + u0.z; ar[3] += r0.w + u0.w;
            ar[4] += r1.x + u1.x; ar[5] += r1.y + u1.y; ar[6] += r1.z + u1.z; ar[7] += r1.w + u1.w;
        } else if (id >= 56 && id < 72) {
            // ---- action token: store base+street now, defer MLP + actor/atype to tail ----
            if (lane == 0) {
                const int k = atomicAdd(&s_acnt, 1);
                s_alist[k] = t;
            }
        } else if (id == 1) {
            // ---- ctx token: defer to tail ----
            if (lane == 0) {
                const int k = atomicAdd(&s_ccnt, 1);
                s_clist[k] = t;
            }
        }

        // ---- game MLP: sequence position 0 only (256 occurrences total) ----
        if ((t & 511) == 0) {
            const int n = t >> 9;
            const float* c0 = cf + (size_t)n * 512 * 9;
            const float sb = __ldg(c0), bb = __ldg(c0 + 1), po = __ldg(c0 + 2);
            const float scale = 100.f * bb;
            const float ssg = (scale == 0.f) ? 1e-8f : scale;
            const float f3 = bb / ssg, f4 = sb / ssg;
            float h[8];
            {
                const float4* bbp = reinterpret_cast<const float4*>(game_b) + lq;
                const float4 hb0 = __ldg(bbp), hb1 = __ldg(bbp + 1);
                h[0]=hb0.x; h[1]=hb0.y; h[2]=hb0.z; h[3]=hb0.w;
                h[4]=hb1.x; h[5]=hb1.y; h[6]=hb1.z; h[7]=hb1.w;
            }
#pragma unroll
            for (int kk = 0; kk < 8; ++kk) {
                const float* wr = game_W + (size_t)(l8 + kk) * 5;
                float s = h[kk];
                s = fmaf(__ldg(wr + 0), sb, s);
                s = fmaf(__ldg(wr + 1), bb, s);
                s = fmaf(__ldg(wr + 2), po, s);
                s = fmaf(__ldg(wr + 3), f3, s);
                s = fmaf(__ldg(wr + 4), f4, s);
                h[kk] = s;
            }
            float mu, rs;
            warp_ln(h, mu, rs);
            const float4* gp = reinterpret_cast<const float4*>(game_g)  + lq;
            const float4* ep = reinterpret_cast<const float4*>(game_be) + lq;
            const float4 g0 = __ldg(gp), g1 = __ldg(gp + 1);
            const float4 e0 = __ldg(ep), e1 = __ldg(ep + 1);
            ar[0] += fmaxf(fmaf((h[0] - mu) * rs, g0.x, e0.x), 0.f);
            ar[1] += fmaxf(fmaf((h[1] - mu) * rs, g0.y, e0.y), 0.f);
            ar[2] += fmaxf(fmaf((h[2] - mu) * rs, g0.z, e0.z), 0.f);
            ar[3] += fmaxf(fmaf((h[3] - mu) * rs, g0.w, e0.w), 0.f);
            ar[4] += fmaxf(fmaf((h[4] - mu) * rs, g1.x, e1.x), 0.f);
            ar[5] += fmaxf(fmaf((h[5] - mu) * rs, g1.y, e1.y), 0.f);
            ar[6] += fmaxf(fmaf((h[6] - mu) * rs, g1.z, e1.z), 0.f);
            ar[7] += fmaxf(fmaf((h[7] - mu) * rs, g1.w, e1.w), 0.f);
        }

        // ---- store (pad -> 0), vectorized ----
        float4 o0, o1;
        if (pad) {
            o0 = make_float4(0.f, 0.f, 0.f, 0.f);
            o1 = o0;
        } else {
            o0 = make_float4(ar[0], ar[1], ar[2], ar[3]);
            o1 = make_float4(ar[4], ar[5], ar[6], ar[7]);
        }
        float4* op = reinterpret_cast<float4*>(out) + (size_t)t * 64 + lq;
        op[0] = o0;
        op[1] = o1;

        t = tn; raw = raw_n; st = st_n; b0 = b0n; b1 = b1n;
    }

    // =================== CTA tail 1: action tokens, thread-owns-dim, weights in regs ===================
    __syncthreads();                 // lists complete + loop stores ordered before RMW
    const int ma = s_acnt;
    if (ma > 0) {
        float lw[16];
        {
            const float4* wq = reinterpret_cast<const float4*>(legal_W) + tid * 4;
            const float4 q0 = __ldg(wq), q1 = __ldg(wq + 1), q2 = __ldg(wq + 2), q3 = __ldg(wq + 3);
            lw[0]=q0.x; lw[1]=q0.y; lw[2]=q0.z;  lw[3]=q0.w;
            lw[4]=q1.x; lw[5]=q1.y; lw[6]=q1.z;  lw[7]=q1.w;
            lw[8]=q2.x; lw[9]=q2.y; lw[10]=q2.z; lw[11]=q2.w;
            lw[12]=q3.x; lw[13]=q3.y; lw[14]=q3.z; lw[15]=q3.w;
        }
        const float lb  = __ldg(legal_b  + tid);
        const float lg  = __ldg(legal_g  + tid);
        const float lbe = __ldg(legal_be + tid);

        for (int base = 0; base < ma; base += ACT_J) {
            const int J = (ma - base < ACT_J) ? (ma - base) : ACT_J;

            // warp w loads x[16] of token base+w
            if (wid < J && lane < 16) {
                const int tt = s_alist[base + wid];
                s_x[wid][lane] = __ldg(legal_masks + (size_t)tt * 16 + lane);
            }
            __syncthreads();

            float h[ACT_J];
#pragma unroll
            for (int j = 0; j < ACT_J; ++j) {
                float s = lb;
#pragma unroll
                for (int k = 0; k < 16; ++k) s = fmaf(lw[k], s_x[j][k], s);
                h[j] = s;
            }

            // batched block LayerNorm
#pragma unroll
            for (int j = 0; j < ACT_J; ++j) {
                float a = h[j], b = h[j] * h[j];
#pragma unroll
                for (int o = 16; o; o >>= 1) {
                    a += __shfl_xor_sync(0xffffffffu, a, o);
                    b += __shfl_xor_sync(0xffffffffu, b, o);
                }
                if (lane == 0) { s_red[wid][j][0] = a; s_red[wid][j][1] = b; }
            }
            __syncthreads();
            if (tid < ACT_J) {
                float t1 = 0.f, t2 = 0.f;
#pragma unroll
                for (int w = 0; w < 8; ++w) { t1 += s_red[w][tid][0]; t2 += s_red[w][tid][1]; }
                const float mu  = t1 * (1.f / 256.f);
                const float var = t2 * (1.f / 256.f) - mu * mu;
                s_ms[tid][0] = mu;
                s_ms[tid][1] = rsqrtf(var + 1e-5f);
            }
            __syncthreads();

            // epilogue: actor + atype + relu(LN) onto already-stored base+street
            for (int j = 0; j < J; ++j) {
                const int tt = s_alist[base + j];
                const int idj = __ldg(token_ids + tt);           // in [56,72)
                int ac = __ldg(action_actors + tt); ac = ac < 0 ? 0 : (ac > 1 ? 1 : ac);
                const float av = __ldg(actor_emb + ac * 256 + tid);
                const float yv = __ldg(atype_emb + (idj - 56) * 256 + tid);
                const float v  = fmaf((h[j] - s_ms[j][0]) * s_ms[j][1], lg, lbe);
                out[(size_t)tt * 256 + tid] += av + yv + fmaxf(v, 0.f);
            }
            __syncthreads();   // s_x/s_red reuse guard
        }
    }

    // =================== CTA tail 2: ctx tokens, J-batched over one Wt stream ===================
    const int m = s_ccnt;
    if (m == 0) return;

    const float hb = __ldg(ctx_b  + tid);
    const float cg = __ldg(ctx_g  + tid);
    const float ce = __ldg(ctx_be + tid);
    const float* wt = g_Wt + tid;

    for (int base = 0; base < m; base += CTX_J) {
        const int J = (m - base < CTX_J) ? (m - base) : CTX_J;

        if (wid < J) {
            const int tt = s_clist[base + wid];
            const int n  = tt >> 9;
            const float* c0 = cf + (size_t)n * 512 * 9;
            const float* cp = cf + (size_t)tt * 9;
            const float bb = __ldg(c0 + 1);
            const float scale = 100.f * bb;
            const float ssafe   = (scale == 0.f) ? 1.f : scale;
            const float bbsafe  = (bb == 0.f) ? 1.f : bb;
            const float pot     = __ldg(cp);
            const float potsafe = (pot == 0.f) ? 1.f : pot;
#pragma unroll
            for (int i = 0; i < 5; ++i) {
                const int idx = lane + 32 * i;
                if (idx < 143) {
                    const int fi = idx / 11;
                    const int ps = idx - fi * 11;
                    const int si = (fi < 9) ? fi : ((fi < 11) ? fi - 8 : fi - 10);
                    const float num = __ldg(cp + si);
                    float den = ssafe;
                    if (fi == 5 || fi == 6)       den = 1.f;
                    else if (fi == 9 || fi == 10) den = bbsafe;
                    else if (fi >= 11)            den = potsafe;
                    const float pv = num / den;
                    float val;
                    if (ps == 0)      val = pv;
                    else if (ps <= 5) val = sinpif(pv * (float)(1 << (ps - 1)));
                    else              val = cospif(pv * (float)(1 << (ps - 6)));
                    s_ca[wid][idx] = val;
                } else if (idx < 144) {
                    s_ca[wid][idx] = 0.f;
                }
            }
        }
        __syncthreads();

        float h[CTX_J];
#pragma unroll
        for (int j = 0; j < CTX_J; ++j) h[j] = hb;
        int k = 0;
        for (; k + 4 <= 143; k += 4) {
            const float w0 = wt[(k + 0) * 256];
            const float w1 = wt[(k + 1) * 256];
            const float w2 = wt[(k + 2) * 256];
            const float w3 = wt[(k + 3) * 256];
#pragma unroll
            for (int j = 0; j < CTX_J; ++j) {
                h[j] = fmaf(s_ca[j][k + 0], w0, h[j]);
                h[j] = fmaf(s_ca[j][k + 1], w1, h[j]);
                h[j] = fmaf(s_ca[j][k + 2], w2, h[j]);
                h[j] = fmaf(s_ca[j][k + 3], w3, h[j]);
            }
        }
        for (; k < 143; ++k) {
            const float w0 = wt[k * 256];
#pragma unroll
            for (int j = 0; j < CTX_J; ++j) h[j] = fmaf(s_ca[j][k], w0, h[j]);
        }

#pragma unroll
        for (int j = 0; j < CTX_J; ++j) {
            float a = h[j], b = h[j] * h[j];
#pragma unroll
            for (int o = 16; o; o >>= 1) {
                a += __shfl_xor_sync(0xffffffffu, a, o);
                b += __shfl_xor_sync(0xffffffffu, b, o);
            }
            if (lane == 0) { s_red[wid][j][0] = a; s_red[wid][j][1] = b; }
        }
        __syncthreads();
        if (tid < CTX_J) {
            float t1 = 0.f, t2 = 0.f;
#pragma unroll
            for (int w = 0; w < 8; ++w) { t1 += s_red[w][tid][0]; t2 += s_red[w][tid][1]; }
            const float mu  = t1 * (1.f / 256.f);
            const float var = t2 * (1.f / 256.f) - mu * mu;
            s_ms[tid][0] = mu;
            s_ms[tid][1] = rsqrtf(var + 1e-5f);
        }
        __syncthreads();

        for (int j = 0; j < J; ++j) {
            const int tt = s_clist[base + j];
            const float v = fmaf((h[j] - s_ms[j][0]) * s_ms[j][1], cg, ce);
            out[(size_t)tt * 256 + tid] += fmaxf(v, 0.f);
        }
        __syncthreads();   // s_ca/s_red reuse guard
    }
}

} // namespace

extern "C" void kernel_launch(void* const* d_in, const int* in_sizes, int n_in,
                              void* d_out, int out_size)
{
    const int tokens = in_sizes[0];   // N*S

    poker_fused_kernel<<<NB_MAIN, 256>>>(
        (const int*)  d_in[0],   // token_ids
        (const int*)  d_in[1],   // token_streets
        (const int*)  d_in[2],   // card_ranks
        (const int*)  d_in[3],   // card_suits
        (const int*)  d_in[4],   // action_actors
        (const float*)d_in[5],   // action_legal_masks
        (const float*)d_in[6],   // context_features
        (const float*)d_in[7],   // base_emb
        (const float*)d_in[8],   // street_emb
        (const float*)d_in[9],   // rank_emb
        (const float*)d_in[10],  // suit_emb
        (const float*)d_in[11],  // actor_emb
        (const float*)d_in[12],  // atype_emb
        (const float*)d_in[13],  // legal_W
        (const float*)d_in[14],  // legal_b
        (const float*)d_in[15],  // legal_g
        (const float*)d_in[16],  // legal_beta
        (const float*)d_in[17],  // game_W
        (const float*)d_in[18],  // game_b
        (const float*)d_in[19],  // game_g
        (const float*)d_in[20],  // game_beta
        (const float*)d_in[21],  // ctx_W
        (const float*)d_in[22],  // ctx_b
        (const float*)d_in[23],  // ctx_g
        (const float*)d_in[24],  // ctx_beta
        (float*)d_out,
        tokens);
}

// round 15
// speedup vs baseline: 1.0824x; 1.0824x over previous
#include <cuda_runtime.h>
#include <cstdint>
#include <cstddef>

namespace {

constexpr int PAD_ID  = 72;      // VOCAB
constexpr int NB_MAIN = 592;     // 4 CTAs/SM * 148 SMs — exactly one wave
constexpr int CTX_J   = 4;       // ctx tokens per Wt pass
constexpr int ACT_J   = 8;       // action tokens per tail pass
constexpr int LSIZE   = 232;     // >= max tokens one CTA can own (8 warps * 28)
constexpr int GFLAG   = 1 << 30; // marks action tokens already stored by the loop (game pos)

// ctx_W transposed: g_Wt[k][d] = ctx_W[d][k]  (143 x 256 = 146 KB)
__device__ float g_Wt[143 * 256];

// warp LayerNorm stats over 256 values (8 per lane)
__device__ __forceinline__ void warp_ln(const float* h, float& mu, float& rs)
{
    float s1 = 0.f, s2 = 0.f;
#pragma unroll
    for (int k = 0; k < 8; ++k) { s1 += h[k]; s2 = fmaf(h[k], h[k], s2); }
#pragma unroll
    for (int o = 16; o; o >>= 1) {
        s1 += __shfl_xor_sync(0xffffffffu, s1, o);
        s2 += __shfl_xor_sync(0xffffffffu, s2, o);
    }
    mu = s1 * (1.f / 256.f);
    float var = s2 * (1.f / 256.f) - mu * mu;
    rs = rsqrtf(var + 1e-5f);
}

// ====== single fused kernel: loop stores non-action rows; tails own action + ctx MLPs ======
__global__ __launch_bounds__(256, 4) void poker_fused_kernel(
    const int*   __restrict__ token_ids,
    const int*   __restrict__ token_streets,
    const int*   __restrict__ card_ranks,
    const int*   __restrict__ card_suits,
    const int*   __restrict__ action_actors,
    const float* __restrict__ legal_masks,   // [T,16]
    const float* __restrict__ cf,            // [T,9]
    const float* __restrict__ base_emb,      // [73,256]
    const float* __restrict__ street_emb,    // [4,256]
    const float* __restrict__ rank_emb,      // [13,256]
    const float* __restrict__ suit_emb,      // [4,256]
    const float* __restrict__ actor_emb,     // [2,256]
    const float* __restrict__ atype_emb,     // [16,256]
    const float* __restrict__ legal_W,       // [256,16]
    const float* __restrict__ legal_b,
    const float* __restrict__ legal_g,
    const float* __restrict__ legal_be,
    const float* __restrict__ game_W,        // [256,5]
    const float* __restrict__ game_b,
    const float* __restrict__ game_g,
    const float* __restrict__ game_be,
    const float* __restrict__ ctx_W,         // [256,143] (transposed into g_Wt)
    const float* __restrict__ ctx_b,
    const float* __restrict__ ctx_g,
    const float* __restrict__ ctx_be,
    float*       __restrict__ out,           // [T,256]
    int tokens)
{
    __shared__ int    s_alist[LSIZE];
    __shared__ int    s_clist[LSIZE];
    __shared__ int    s_acnt, s_ccnt;
    __shared__ float  s_x[ACT_J][16];
    __shared__ float  s_ca[CTX_J][144];
    __shared__ float  s_red[8][ACT_J][2];
    __shared__ float  s_ms[ACT_J][2];

    const int tid  = threadIdx.x;
    const int lane = tid & 31;
    const int wid  = tid >> 5;

    // ---- fold the ctx_W transpose into the first 143 blocks.
    // Safe: grid is exactly one co-resident wave (launch_bounds-guaranteed); writes
    // finish in ~2k cycles; first g_Wt read is after each CTA's full main loop.
    if (blockIdx.x < 143) {
        const int k = blockIdx.x;
        g_Wt[k * 256 + tid] = __ldg(ctx_W + tid * 143 + k);
    }

    if (tid == 0) { s_acnt = 0; s_ccnt = 0; }
    __syncthreads();

    const int gwarp = blockIdx.x * 8 + wid;
    const int nwarp = gridDim.x * 8;
    const int l8    = lane << 3;
    const int lq    = lane * 2;

    // software pipeline: ids AND base_emb gather issued one iteration ahead
    int t   = gwarp;
    int raw = 0, st = 0;
    float4 b0 = make_float4(0.f,0.f,0.f,0.f), b1 = b0;
    if (t < tokens) {
        raw = __ldg(token_ids + t);
        st  = __ldg(token_streets + t);
        const int id0 = raw < 0 ? PAD_ID : raw;
        const float4* bp = reinterpret_cast<const float4*>(base_emb) + id0 * 64 + lq;
        b0 = __ldg(bp); b1 = __ldg(bp + 1);
    }

    while (t < tokens) {
        const int tn = t + nwarp;
        int raw_n = 0, st_n = 0;
        float4 b0n = make_float4(0.f,0.f,0.f,0.f), b1n = b0n;
        if (tn < tokens) {
            raw_n = __ldg(token_ids + tn);
            st_n  = __ldg(token_streets + tn);
            const int idn = raw_n < 0 ? PAD_ID : raw_n;
            const float4* bpn = reinterpret_cast<const float4*>(base_emb) + idn * 64 + lq;
            b0n = __ldg(bpn); b1n = __ldg(bpn + 1);
        }

        const bool pad     = raw < 0;
        const int  id      = pad ? PAD_ID : raw;
        const bool isAct   = (id >= 56 && id < 72);
        const bool gamePos = (t & 511) == 0;

        if (isAct) {
            // defer; mark entries whose row the loop stores (game position)
            if (lane == 0) {
                const int k = atomicAdd(&s_acnt, 1);
                s_alist[k] = gamePos ? (t | GFLAG) : t;
            }
        } else if (id == 1) {
            if (lane == 0) {
                const int k = atomicAdd(&s_ccnt, 1);
                s_clist[k] = t;
            }
        }

        if (!isAct || gamePos) {
            float ar[8];
            {
                const float4* sp = reinterpret_cast<const float4*>(street_emb) + st * 64 + lq;
                const float4 s0 = __ldg(sp), s1 = __ldg(sp + 1);
                ar[0] = b0.x + s0.x; ar[1] = b0.y + s0.y; ar[2] = b0.z + s0.z; ar[3] = b0.w + s0.w;
                ar[4] = b1.x + s1.x; ar[5] = b1.y + s1.y; ar[6] = b1.z + s1.z; ar[7] = b1.w + s1.w;
            }

            if (id >= 4 && id < 56) {
                // ---- card token ----
                int rk = __ldg(card_ranks + t); rk = rk < 0 ? 0 : (rk > 12 ? 12 : rk);
                int su = __ldg(card_suits + t); su = su < 0 ? 0 : (su > 3  ? 3  : su);
                const float4* rp = reinterpret_cast<const float4*>(rank_emb) + rk * 64 + lq;
                const float4* up = reinterpret_cast<const float4*>(suit_emb) + su * 64 + lq;
                const float4 r0 = __ldg(rp), r1 = __ldg(rp + 1);
                const float4 u0 = __ldg(up), u1 = __ldg(up + 1);
                ar[0] += r0.x + u0.x; ar[1] += r0.y + u0.y; ar[2] += r0.z + u0.z; ar[3] += r0.w + u0.w;
                ar[4] += r1.x + u1.x; ar[5] += r1.y + u1.y; ar[6] += r1.z + u1.z; ar[7] += r1.w + u1.w;
            }

            // ---- game MLP: sequence position 0 only ----
            if (gamePos) {
                const int n = t >> 9;
                const float* c0 = cf + (size_t)n * 512 * 9;
                const float sb = __ldg(c0), bb = __ldg(c0 + 1), po = __ldg(c0 + 2);
                const float scale = 100.f * bb;
                const float ssg = (scale == 0.f) ? 1e-8f : scale;
                const float f3 = bb / ssg, f4 = sb / ssg;
                float h[8];
                {
                    const float4* bbp = reinterpret_cast<const float4*>(game_b) + lq;
                    const float4 hb0 = __ldg(bbp), hb1 = __ldg(bbp + 1);
                    h[0]=hb0.x; h[1]=hb0.y; h[2]=hb0.z; h[3]=hb0.w;
                    h[4]=hb1.x; h[5]=hb1.y; h[6]=hb1.z; h[7]=hb1.w;
                }
#pragma unroll
                for (int kk = 0; kk < 8; ++kk) {
                    const float* wr = game_W + (size_t)(l8 + kk) * 5;
                    float s = h[kk];
                    s = fmaf(__ldg(wr + 0), sb, s);
                    s = fmaf(__ldg(wr + 1), bb, s);
                    s = fmaf(__ldg(wr + 2), po, s);
                    s = fmaf(__ldg(wr + 3), f3, s);
                    s = fmaf(__ldg(wr + 4), f4, s);
                    h[kk] = s;
                }
                float mu, rs;
                warp_ln(h, mu, rs);
                const float4* gp = reinterpret_cast<const float4*>(game_g)  + lq;
                const float4* ep = reinterpret_cast<const float4*>(game_be) + lq;
                const float4 g0 = __ldg(gp), g1 = __ldg(gp + 1);
                const float4 e0 = __ldg(ep), e1 = __ldg(ep + 1);
                ar[0] += fmaxf(fmaf((h[0] - mu) * rs, g0.x, e0.x), 0.f);
                ar[1] += fmaxf(fmaf((h[1] - mu) * rs, g0.y, e0.y), 0.f);
                ar[2] += fmaxf(fmaf((h[2] - mu) * rs, g0.z, e0.z), 0.f);
                ar[3] += fmaxf(fmaf((h[3] - mu) * rs, g0.w, e0.w), 0.f);
                ar[4] += fmaxf(fmaf((h[4] - mu) * rs, g1.x, e1.x), 0.f);
                ar[5] += fmaxf(fmaf((h[5] - mu) * rs, g1.y, e1.y), 0.f);
                ar[6] += fmaxf(fmaf((h[6] - mu) * rs, g1.z, e1.z), 0.f);
                ar[7] += fmaxf(fmaf((h[7] - mu) * rs, g1.w, e1.w), 0.f);
            }

            // ---- store (pad -> 0), vectorized ----
            float4 o0, o1;
            if (pad) {
                o0 = make_float4(0.f, 0.f, 0.f, 0.f);
                o1 = o0;
            } else {
                o0 = make_float4(ar[0], ar[1], ar[2], ar[3]);
                o1 = make_float4(ar[4], ar[5], ar[6], ar[7]);
            }
            float4* op = reinterpret_cast<float4*>(out) + (size_t)t * 64 + lq;
            op[0] = o0;
            op[1] = o1;
        }

        t = tn; raw = raw_n; st = st_n; b0 = b0n; b1 = b1n;
    }

    // ============ CTA tail 1: action tokens — single full-row write, weights in regs ============
    __syncthreads();                 // lists complete + loop stores ordered before tail
    const int ma = s_acnt;
    if (ma > 0) {
        float lw[16];
        {
            const float4* wq = reinterpret_cast<const float4*>(legal_W) + tid * 4;
            const float4 q0 = __ldg(wq), q1 = __ldg(wq + 1), q2 = __ldg(wq + 2), q3 = __ldg(wq + 3);
            lw[0]=q0.x; lw[1]=q0.y; lw[2]=q0.z;  lw[3]=q0.w;
            lw[4]=q1.x; lw[5]=q1.y; lw[6]=q1.z;  lw[7]=q1.w;
            lw[8]=q2.x; lw[9]=q2.y; lw[10]=q2.z; lw[11]=q2.w;
            lw[12]=q3.x; lw[13]=q3.y; lw[14]=q3.z; lw[15]=q3.w;
        }
        const float lb  = __ldg(legal_b  + tid);
        const float lg  = __ldg(legal_g  + tid);
        const float lbe = __ldg(legal_be + tid);

        for (int base = 0; base < ma; base += ACT_J) {
            const int J = (ma - base < ACT_J) ? (ma - base) : ACT_J;

            // warp w loads x[16] of token base+w
            if (wid < J && lane < 16) {
                const int tt = s_alist[base + wid] & ~GFLAG;
                s_x[wid][lane] = __ldg(legal_masks + (size_t)tt * 16 + lane);
            }
            __syncthreads();

            float h[ACT_J];
#pragma unroll
            for (int j = 0; j < ACT_J; ++j) {
                float s = lb;
#pragma unroll
                for (int k = 0; k < 16; ++k) s = fmaf(lw[k], s_x[j][k], s);
                h[j] = s;
            }

            // batched block LayerNorm
#pragma unroll
            for (int j = 0; j < ACT_J; ++j) {
                float a = h[j], b = h[j] * h[j];
#pragma unroll
                for (int o = 16; o; o >>= 1) {
                    a += __shfl_xor_sync(0xffffffffu, a, o);
                    b += __shfl_xor_sync(0xffffffffu, b, o);
                }
                if (lane == 0) { s_red[wid][j][0] = a; s_red[wid][j][1] = b; }
            }
            __syncthreads();
            if (tid < ACT_J) {
                float t1 = 0.f, t2 = 0.f;
#pragma unroll
                for (int w = 0; w < 8; ++w) { t1 += s_red[w][tid][0]; t2 += s_red[w][tid][1]; }
                const float mu  = t1 * (1.f / 256.f);
                const float var = t2 * (1.f / 256.f) - mu * mu;
                s_ms[tid][0] = mu;
                s_ms[tid][1] = rsqrtf(var + 1e-5f);
            }
            __syncthreads();

            // epilogue: compose full row (or add onto loop-stored game row)
            for (int j = 0; j < J; ++j) {
                const int e  = s_alist[base + j];
                const bool flagged = (e & GFLAG) != 0;
                const int tt = e & ~GFLAG;
                const int idj = __ldg(token_ids + tt);           // in [56,72)
                int ac = __ldg(action_actors + tt); ac = ac < 0 ? 0 : (ac > 1 ? 1 : ac);
                float val = __ldg(actor_emb + ac * 256 + tid)
                          + __ldg(atype_emb + (idj - 56) * 256 + tid)
                          + fmaxf(fmaf((h[j] - s_ms[j][0]) * s_ms[j][1], lg, lbe), 0.f);
                float* od = out + (size_t)tt * 256 + tid;
                if (flagged) {
                    *od += val;                                   // loop stored base+street+game
                } else {
                    const int stj = __ldg(token_streets + tt);
                    val += __ldg(base_emb + idj * 256 + tid)
                         + __ldg(street_emb + stj * 256 + tid);
                    *od = val;                                    // single write
                }
            }
            __syncthreads();   // s_x/s_red reuse guard
        }
    }

    // ============ CTA tail 2: ctx tokens, J-batched over one Wt stream ============
    const int m = s_ccnt;
    if (m == 0) return;

    const float hb = __ldg(ctx_b  + tid);
    const float cg = __ldg(ctx_g  + tid);
    const float ce = __ldg(ctx_be + tid);
    const float* wt = g_Wt + tid;

    for (int base = 0; base < m; base += CTX_J) {
        const int J = (m - base < CTX_J) ? (m - base) : CTX_J;

        if (wid < J) {
            const int tt = s_clist[base + wid];
            const int n  = tt >> 9;
            const float* c0 = cf + (size_t)n * 512 * 9;
            const float* cp = cf + (size_t)tt * 9;
            const float bb = __ldg(c0 + 1);
            const float scale = 100.f * bb;
            const float ssafe   = (scale == 0.f) ? 1.f : scale;
            const float bbsafe  = (bb == 0.f) ? 1.f : bb;
            const float pot     = __ldg(cp);
            const float potsafe = (pot == 0.f) ? 1.f : pot;
#pragma unroll
            for (int i = 0; i < 5; ++i) {
                const int idx = lane + 32 * i;
                if (idx < 143) {
                    const int fi = idx / 11;
                    const int ps = idx - fi * 11;
                    const int si = (fi < 9) ? fi : ((fi < 11) ? fi - 8 : fi - 10);
                    const float num = __ldg(cp + si);
                    float den = ssafe;
                    if (fi == 5 || fi == 6)       den = 1.f;
                    else if (fi == 9 || fi == 10) den = bbsafe;
                    else if (fi >= 11)            den = potsafe;
                    const float pv = num / den;
                    float val;
                    if (ps == 0)      val = pv;
                    else if (ps <= 5) val = sinpif(pv * (float)(1 << (ps - 1)));
                    else              val = cospif(pv * (float)(1 << (ps - 6)));
                    s_ca[wid][idx] = val;
                } else if (idx < 144) {
                    s_ca[wid][idx] = 0.f;
                }
            }
        }
        __syncthreads();

        float h[CTX_J];
#pragma unroll
        for (int j = 0; j < CTX_J; ++j) h[j] = hb;
        int k = 0;
        for (; k + 4 <= 143; k += 4) {
            const float w0 = wt[(k + 0) * 256];
            const float w1 = wt[(k + 1) * 256];
            const float w2 = wt[(k + 2) * 256];
            const float w3 = wt[(k + 3) * 256];
#pragma unroll
            for (int j = 0; j < CTX_J; ++j) {
                h[j] = fmaf(s_ca[j][k + 0], w0, h[j]);
                h[j] = fmaf(s_ca[j][k + 1], w1, h[j]);
                h[j] = fmaf(s_ca[j][k + 2], w2, h[j]);
                h[j] = fmaf(s_ca[j][k + 3], w3, h[j]);
            }
        }
        for (; k < 143; ++k) {
            const float w0 = wt[k * 256];
#pragma unroll
            for (int j = 0; j < CTX_J; ++j) h[j] = fmaf(s_ca[j][k], w0, h[j]);
        }

#pragma unroll
        for (int j = 0; j < CTX_J; ++j) {
            float a = h[j], b = h[j] * h[j];
#pragma unroll
            for (int o = 16; o; o >>= 1) {
                a += __shfl_xor_sync(0xffffffffu, a, o);
                b += __shfl_xor_sync(0xffffffffu, b, o);
            }
            if (lane == 0) { s_red[wid][j][0] = a; s_red[wid][j][1] = b; }
        }
        __syncthreads();
        if (tid < CTX_J) {
            float t1 = 0.f, t2 = 0.f;
#pragma unroll
            for (int w = 0; w < 8; ++w) { t1 += s_red[w][tid][0]; t2 += s_red[w][tid][1]; }
            const float mu  = t1 * (1.f / 256.f);
            const float var = t2 * (1.f / 256.f) - mu * mu;
            s_ms[tid][0] = mu;
            s_ms[tid][1] = rsqrtf(var + 1e-5f);
        }
        __syncthreads();

        for (int j = 0; j < J; ++j) {
            const int tt = s_clist[base + j];
            const float v = fmaf((h[j] - s_ms[j][0]) * s_ms[j][1], cg, ce);
            out[(size_t)tt * 256 + tid] += fmaxf(v, 0.f);
        }
        __syncthreads();   // s_ca/s_red reuse guard
    }
}

} // namespace

extern "C" void kernel_launch(void* const* d_in, const int* in_sizes, int n_in,
                              void* d_out, int out_size)
{
    const int tokens = in_sizes[0];   // N*S

    poker_fused_kernel<<<NB_MAIN, 256>>>(
        (const int*)  d_in[0],   // token_ids
        (const int*)  d_in[1],   // token_streets
        (const int*)  d_in[2],   // card_ranks
        (const int*)  d_in[3],   // card_suits
        (const int*)  d_in[4],   // action_actors
        (const float*)d_in[5],   // action_legal_masks
        (const float*)d_in[6],   // context_features
        (const float*)d_in[7],   // base_emb
        (const float*)d_in[8],   // street_emb
        (const float*)d_in[9],   // rank_emb
        (const float*)d_in[10],  // suit_emb
        (const float*)d_in[11],  // actor_emb
        (const float*)d_in[12],  // atype_emb
        (const float*)d_in[13],  // legal_W
        (const float*)d_in[14],  // legal_b
        (const float*)d_in[15],  // legal_g
        (const float*)d_in[16],  // legal_beta
        (const float*)d_in[17],  // game_W
        (const float*)d_in[18],  // game_b
        (const float*)d_in[19],  // game_g
        (const float*)d_in[20],  // game_beta
        (const float*)d_in[21],  // ctx_W
        (const float*)d_in[22],  // ctx_b
        (const float*)d_in[23],  // ctx_g
        (const float*)d_in[24],  // ctx_beta
        (float*)d_out,
        tokens);
}

// round 16
// speedup vs baseline: 1.0841x; 1.0016x over previous
#include <cuda_runtime.h>
#include <cstdint>
#include <cstddef>

namespace {

constexpr int PAD_ID  = 72;      // VOCAB
constexpr int NB_MAIN = 740;     // 5 CTAs/SM * 148 SMs — exactly one wave
constexpr int CTX_J   = 4;       // ctx tokens per Wt pass
constexpr int ACT_J   = 8;       // action tokens per tail pass
constexpr int LSIZE   = 232;     // >= max tokens one CTA can own (8 warps * 23 = 184)
constexpr int GFLAG   = 1 << 30; // marks action tokens already stored by the loop (game pos)

// ctx_W transposed: g_Wt[k][d] = ctx_W[d][k]  (143 x 256 = 146 KB)
__device__ float g_Wt[143 * 256];

// warp LayerNorm stats over 256 values (8 per lane)
__device__ __forceinline__ void warp_ln(const float* h, float& mu, float& rs)
{
    float s1 = 0.f, s2 = 0.f;
#pragma unroll
    for (int k = 0; k < 8; ++k) { s1 += h[k]; s2 = fmaf(h[k], h[k], s2); }
#pragma unroll
    for (int o = 16; o; o >>= 1) {
        s1 += __shfl_xor_sync(0xffffffffu, s1, o);
        s2 += __shfl_xor_sync(0xffffffffu, s2, o);
    }
    mu = s1 * (1.f / 256.f);
    float var = s2 * (1.f / 256.f) - mu * mu;
    rs = rsqrtf(var + 1e-5f);
}

// ====== single fused kernel: loop stores non-action rows; tails own action + ctx MLPs ======
__global__ __launch_bounds__(256, 5) void poker_fused_kernel(
    const int*   __restrict__ token_ids,
    const int*   __restrict__ token_streets,
    const int*   __restrict__ card_ranks,
    const int*   __restrict__ card_suits,
    const int*   __restrict__ action_actors,
    const float* __restrict__ legal_masks,   // [T,16]
    const float* __restrict__ cf,            // [T,9]
    const float* __restrict__ base_emb,      // [73,256]
    const float* __restrict__ street_emb,    // [4,256]
    const float* __restrict__ rank_emb,      // [13,256]
    const float* __restrict__ suit_emb,      // [4,256]
    const float* __restrict__ actor_emb,     // [2,256]
    const float* __restrict__ atype_emb,     // [16,256]
    const float* __restrict__ legal_W,       // [256,16]
    const float* __restrict__ legal_b,
    const float* __restrict__ legal_g,
    const float* __restrict__ legal_be,
    const float* __restrict__ game_W,        // [256,5]
    const float* __restrict__ game_b,
    const float* __restrict__ game_g,
    const float* __restrict__ game_be,
    const float* __restrict__ ctx_W,         // [256,143] (transposed into g_Wt)
    const float* __restrict__ ctx_b,
    const float* __restrict__ ctx_g,
    const float* __restrict__ ctx_be,
    float*       __restrict__ out,           // [T,256]
    int tokens)
{
    __shared__ int    s_alist[LSIZE];
    __shared__ int    s_clist[LSIZE];
    __shared__ int    s_acnt, s_ccnt;
    __shared__ float  s_x[ACT_J][16];
    __shared__ float  s_ca[CTX_J][144];
    __shared__ float  s_red[8][ACT_J][2];
    __shared__ float  s_ms[ACT_J][2];

    const int tid  = threadIdx.x;
    const int lane = tid & 31;
    const int wid  = tid >> 5;

    // ---- fold the ctx_W transpose into the first 143 blocks.
    // Safe: grid is exactly one co-resident wave (launch_bounds-guaranteed); writes
    // finish in ~2k cycles; first g_Wt read is after each CTA's full main loop.
    if (blockIdx.x < 143) {
        const int k = blockIdx.x;
        g_Wt[k * 256 + tid] = __ldg(ctx_W + tid * 143 + k);
    }

    if (tid == 0) { s_acnt = 0; s_ccnt = 0; }
    __syncthreads();

    const int gwarp = blockIdx.x * 8 + wid;
    const int nwarp = gridDim.x * 8;
    const int l8    = lane << 3;
    const int lq    = lane * 2;

    // software pipeline: ids AND base_emb gather issued one iteration ahead
    int t   = gwarp;
    int raw = 0, st = 0;
    float4 b0 = make_float4(0.f,0.f,0.f,0.f), b1 = b0;
    if (t < tokens) {
        raw = __ldg(token_ids + t);
        st  = __ldg(token_streets + t);
        const int id0 = raw < 0 ? PAD_ID : raw;
        const float4* bp = reinterpret_cast<const float4*>(base_emb) + id0 * 64 + lq;
        b0 = __ldg(bp); b1 = __ldg(bp + 1);
    }

    while (t < tokens) {
        const int tn = t + nwarp;
        int raw_n = 0, st_n = 0;
        float4 b0n = make_float4(0.f,0.f,0.f,0.f), b1n = b0n;
        if (tn < tokens) {
            raw_n = __ldg(token_ids + tn);
            st_n  = __ldg(token_streets + tn);
            const int idn = raw_n < 0 ? PAD_ID : raw_n;
            const float4* bpn = reinterpret_cast<const float4*>(base_emb) + idn * 64 + lq;
            b0n = __ldg(bpn); b1n = __ldg(bpn + 1);
        }

        const bool pad     = raw < 0;
        const int  id      = pad ? PAD_ID : raw;
        const bool isAct   = (id >= 56 && id < 72);
        const bool gamePos = (t & 511) == 0;

        if (isAct) {
            // defer; mark entries whose row the loop stores (game position)
            if (lane == 0) {
                const int k = atomicAdd(&s_acnt, 1);
                s_alist[k] = gamePos ? (t | GFLAG) : t;
            }
        } else if (id == 1) {
            if (lane == 0) {
                const int k = atomicAdd(&s_ccnt, 1);
                s_clist[k] = t;
            }
        }

        if (!isAct || gamePos) {
            float ar[8];
            {
                const float4* sp = reinterpret_cast<const float4*>(street_emb) + st * 64 + lq;
                const float4 s0 = __ldg(sp), s1 = __ldg(sp + 1);
                ar[0] = b0.x + s0.x; ar[1] = b0.y + s0.y; ar[2] = b0.z + s0.z; ar[3] = b0.w + s0.w;
                ar[4] = b1.x + s1.x; ar[5] = b1.y + s1.y; ar[6] = b1.z + s1.z; ar[7] = b1.w + s1.w;
            }

            if (id >= 4 && id < 56) {
                // ---- card token ----
                int rk = __ldg(card_ranks + t); rk = rk < 0 ? 0 : (rk > 12 ? 12 : rk);
                int su = __ldg(card_suits + t); su = su < 0 ? 0 : (su > 3  ? 3  : su);
                const float4* rp = reinterpret_cast<const float4*>(rank_emb) + rk * 64 + lq;
                const float4* up = reinterpret_cast<const float4*>(suit_emb) + su * 64 + lq;
                const float4 r0 = __ldg(rp), r1 = __ldg(rp + 1);
                const float4 u0 = __ldg(up), u1 = __ldg(up + 1);
                ar[0] += r0.x + u0.x; ar[1] += r0.y + u0.y; ar[2] += r0.z + u0.z; ar[3] += r0.w + u0.w;
                ar[4] += r1.x + u1.x; ar[5] += r1.y + u1.y; ar[6] += r1.z + u1.z; ar[7] += r1.w + u1.w;
            }

            // ---- game MLP: sequence position 0 only ----
            if (gamePos) {
                const int n = t >> 9;
                const float* c0 = cf + (size_t)n * 512 * 9;
                const float sb = __ldg(c0), bb = __ldg(c0 + 1), po = __ldg(c0 + 2);
                const float scale = 100.f * bb;
                const float ssg = (scale == 0.f) ? 1e-8f : scale;
                const float f3 = bb / ssg, f4 = sb / ssg;
                float h[8];
                {
                    const float4* bbp = reinterpret_cast<const float4*>(game_b) + lq;
                    const float4 hb0 = __ldg(bbp), hb1 = __ldg(bbp + 1);
                    h[0]=hb0.x; h[1]=hb0.y; h[2]=hb0.z; h[3]=hb0.w;
                    h[4]=hb1.x; h[5]=hb1.y; h[6]=hb1.z; h[7]=hb1.w;
                }
#pragma unroll
                for (int kk = 0; kk < 8; ++kk) {
                    const float* wr = game_W + (size_t)(l8 + kk) * 5;
                    float s = h[kk];
                    s = fmaf(__ldg(wr + 0), sb, s);
                    s = fmaf(__ldg(wr + 1), bb, s);
                    s = fmaf(__ldg(wr + 2), po, s);
                    s = fmaf(__ldg(wr + 3), f3, s);
                    s = fmaf(__ldg(wr + 4), f4, s);
                    h[kk] = s;
                }
                float mu, rs;
                warp_ln(h, mu, rs);
                const float4* gp = reinterpret_cast<const float4*>(game_g)  + lq;
                const float4* ep = reinterpret_cast<const float4*>(game_be) + lq;
                const float4 g0 = __ldg(gp), g1 = __ldg(gp + 1);
                const float4 e0 = __ldg(ep), e1 = __ldg(ep + 1);
                ar[0] += fmaxf(fmaf((h[0] - mu) * rs, g0.x, e0.x), 0.f);
                ar[1] += fmaxf(fmaf((h[1] - mu) * rs, g0.y, e0.y), 0.f);
                ar[2] += fmaxf(fmaf((h[2] - mu) * rs, g0.z, e0.z), 0.f);
                ar[3] += fmaxf(fmaf((h[3] - mu) * rs, g0.w, e0.w), 0.f);
                ar[4] += fmaxf(fmaf((h[4] - mu) * rs, g1.x, e1.x), 0.f);
                ar[5] += fmaxf(fmaf((h[5] - mu) * rs, g1.y, e1.y), 0.f);
                ar[6] += fmaxf(fmaf((h[6] - mu) * rs, g1.z, e1.z), 0.f);
                ar[7] += fmaxf(fmaf((h[7] - mu) * rs, g1.w, e1.w), 0.f);
            }

            // ---- store (pad -> 0), vectorized ----
            float4 o0, o1;
            if (pad) {
                o0 = make_float4(0.f, 0.f, 0.f, 0.f);
                o1 = o0;
            } else {
                o0 = make_float4(ar[0], ar[1], ar[2], ar[3]);
                o1 = make_float4(ar[4], ar[5], ar[6], ar[7]);
            }
            float4* op = reinterpret_cast<float4*>(out) + (size_t)t * 64 + lq;
            op[0] = o0;
            op[1] = o1;
        }

        t = tn; raw = raw_n; st = st_n; b0 = b0n; b1 = b1n;
    }

    // ============ CTA tail 1: action tokens — single full-row write, weights in regs ============
    __syncthreads();                 // lists complete + loop stores ordered before tail
    const int ma = s_acnt;
    if (ma > 0) {
        float lw[16];
        {
            const float4* wq = reinterpret_cast<const float4*>(legal_W) + tid * 4;
            const float4 q0 = __ldg(wq), q1 = __ldg(wq + 1), q2 = __ldg(wq + 2), q3 = __ldg(wq + 3);
            lw[0]=q0.x; lw[1]=q0.y; lw[2]=q0.z;  lw[3]=q0.w;
            lw[4]=q1.x; lw[5]=q1.y; lw[6]=q1.z;  lw[7]=q1.w;
            lw[8]=q2.x; lw[9]=q2.y; lw[10]=q2.z; lw[11]=q2.w;
            lw[12]=q3.x; lw[13]=q3.y; lw[14]=q3.z; lw[15]=q3.w;
        }
        const float lb  = __ldg(legal_b  + tid);
        const float lg  = __ldg(legal_g  + tid);
        const float lbe = __ldg(legal_be + tid);

        for (int base = 0; base < ma; base += ACT_J) {
            const int J = (ma - base < ACT_J) ? (ma - base) : ACT_J;

            // warp w loads x[16] of token base+w
            if (wid < J && lane < 16) {
                const int tt = s_alist[base + wid] & ~GFLAG;
                s_x[wid][lane] = __ldg(legal_masks + (size_t)tt * 16 + lane);
            }
            __syncthreads();

            float h[ACT_J];
#pragma unroll
            for (int j = 0; j < ACT_J; ++j) {
                float s = lb;
#pragma unroll
                for (int k = 0; k < 16; ++k) s = fmaf(lw[k], s_x[j][k], s);
                h[j] = s;
            }

            // batched block LayerNorm
#pragma unroll
            for (int j = 0; j < ACT_J; ++j) {
                float a = h[j], b = h[j] * h[j];
#pragma unroll
                for (int o = 16; o; o >>= 1) {
                    a += __shfl_xor_sync(0xffffffffu, a, o);
                    b += __shfl_xor_sync(0xffffffffu, b, o);
                }
                if (lane == 0) { s_red[wid][j][0] = a; s_red[wid][j][1] = b; }
            }
            __syncthreads();
            if (tid < ACT_J) {
                float t1 = 0.f, t2 = 0.f;
#pragma unroll
                for (int w = 0; w < 8; ++w) { t1 += s_red[w][tid][0]; t2 += s_red[w][tid][1]; }
                const float mu  = t1 * (1.f / 256.f);
                const float var = t2 * (1.f / 256.f) - mu * mu;
                s_ms[tid][0] = mu;
                s_ms[tid][1] = rsqrtf(var + 1e-5f);
            }
            __syncthreads();

            // epilogue: compose full row (or add onto loop-stored game row)
            for (int j = 0; j < J; ++j) {
                const int e  = s_alist[base + j];
                const bool flagged = (e & GFLAG) != 0;
                const int tt = e & ~GFLAG;
                const int idj = __ldg(token_ids + tt);           // in [56,72)
                int ac = __ldg(action_actors + tt); ac = ac < 0 ? 0 : (ac > 1 ? 1 : ac);
                float val = __ldg(actor_emb + ac * 256 + tid)
                          + __ldg(atype_emb + (idj - 56) * 256 + tid)
                          + fmaxf(fmaf((h[j] - s_ms[j][0]) * s_ms[j][1], lg, lbe), 0.f);
                float* od = out + (size_t)tt * 256 + tid;
                if (flagged) {
                    *od += val;                                   // loop stored base+street+game
                } else {
                    const int stj = __ldg(token_streets + tt);
                    val += __ldg(base_emb + idj * 256 + tid)
                         + __ldg(street_emb + stj * 256 + tid);
                    *od = val;                                    // single write
                }
            }
            __syncthreads();   // s_x/s_red reuse guard
        }
    }

    // ============ CTA tail 2: ctx tokens, J-batched over one Wt stream ============
    const int m = s_ccnt;
    if (m == 0) return;

    const float hb = __ldg(ctx_b  + tid);
    const float cg = __ldg(ctx_g  + tid);
    const float ce = __ldg(ctx_be + tid);
    const float* wt = g_Wt + tid;

    for (int base = 0; base < m; base += CTX_J) {
        const int J = (m - base < CTX_J) ? (m - base) : CTX_J;

        if (wid < J) {
            const int tt = s_clist[base + wid];
            const int n  = tt >> 9;
            const float* c0 = cf + (size_t)n * 512 * 9;
            const float* cp = cf + (size_t)tt * 9;
            const float bb = __ldg(c0 + 1);
            const float scale = 100.f * bb;
            const float ssafe   = (scale == 0.f) ? 1.f : scale;
            const float bbsafe  = (bb == 0.f) ? 1.f : bb;
            const float pot     = __ldg(cp);
            const float potsafe = (pot == 0.f) ? 1.f : pot;
#pragma unroll
            for (int i = 0; i < 5; ++i) {
                const int idx = lane + 32 * i;
                if (idx < 143) {
                    const int fi = idx / 11;
                    const int ps = idx - fi * 11;
                    const int si = (fi < 9) ? fi : ((fi < 11) ? fi - 8 : fi - 10);
                    const float num = __ldg(cp + si);
                    float den = ssafe;
                    if (fi == 5 || fi == 6)       den = 1.f;
                    else if (fi == 9 || fi == 10) den = bbsafe;
                    else if (fi >= 11)            den = potsafe;
                    const float pv = num / den;
                    float val;
                    if (ps == 0)      val = pv;
                    else if (ps <= 5) val = sinpif(pv * (float)(1 << (ps - 1)));
                    else              val = cospif(pv * (float)(1 << (ps - 6)));
                    s_ca[wid][idx] = val;
                } else if (idx < 144) {
                    s_ca[wid][idx] = 0.f;
                }
            }
        }
        __syncthreads();

        float h[CTX_J];
#pragma unroll
        for (int j = 0; j < CTX_J; ++j) h[j] = hb;
        int k = 0;
        for (; k + 4 <= 143; k += 4) {
            const float w0 = wt[(k + 0) * 256];
            const float w1 = wt[(k + 1) * 256];
            const float w2 = wt[(k + 2) * 256];
            const float w3 = wt[(k + 3) * 256];
#pragma unroll
            for (int j = 0; j < CTX_J; ++j) {
                h[j] = fmaf(s_ca[j][k + 0], w0, h[j]);
                h[j] = fmaf(s_ca[j][k + 1], w1, h[j]);
                h[j] = fmaf(s_ca[j][k + 2], w2, h[j]);
                h[j] = fmaf(s_ca[j][k + 3], w3, h[j]);
            }
        }
        for (; k < 143; ++k) {
            const float w0 = wt[k * 256];
#pragma unroll
            for (int j = 0; j < CTX_J; ++j) h[j] = fmaf(s_ca[j][k], w0, h[j]);
        }

#pragma unroll
        for (int j = 0; j < CTX_J; ++j) {
            float a = h[j], b = h[j] * h[j];
#pragma unroll
            for (int o = 16; o; o >>= 1) {
                a += __shfl_xor_sync(0xffffffffu, a, o);
                b += __shfl_xor_sync(0xffffffffu, b, o);
            }
            if (lane == 0) { s_red[wid][j][0] = a; s_red[wid][j][1] = b; }
        }
        __syncthreads();
        if (tid < CTX_J) {
            float t1 = 0.f, t2 = 0.f;
#pragma unroll
            for (int w = 0; w < 8; ++w) { t1 += s_red[w][tid][0]; t2 += s_red[w][tid][1]; }
            const float mu  = t1 * (1.f / 256.f);
            const float var = t2 * (1.f / 256.f) - mu * mu;
            s_ms[tid][0] = mu;
            s_ms[tid][1] = rsqrtf(var + 1e-5f);
        }
        __syncthreads();

        for (int j = 0; j < J; ++j) {
            const int tt = s_clist[base + j];
            const float v = fmaf((h[j] - s_ms[j][0]) * s_ms[j][1], cg, ce);
            out[(size_t)tt * 256 + tid] += fmaxf(v, 0.f);
        }
        __syncthreads();   // s_ca/s_red reuse guard
    }
}

} // namespace

extern "C" void kernel_launch(void* const* d_in, const int* in_sizes, int n_in,
                              void* d_out, int out_size)
{
    const int tokens = in_sizes[0];   // N*S

    poker_fused_kernel<<<NB_MAIN, 256>>>(
        (const int*)  d_in[0],   // token_ids
        (const int*)  d_in[1],   // token_streets
        (const int*)  d_in[2],   // card_ranks
        (const int*)  d_in[3],   // card_suits
        (const int*)  d_in[4],   // action_actors
        (const float*)d_in[5],   // action_legal_masks
        (const float*)d_in[6],   // context_features
        (const float*)d_in[7],   // base_emb
        (const float*)d_in[8],   // street_emb
        (const float*)d_in[9],   // rank_emb
        (const float*)d_in[10],  // suit_emb
        (const float*)d_in[11],  // actor_emb
        (const float*)d_in[12],  // atype_emb
        (const float*)d_in[13],  // legal_W
        (const float*)d_in[14],  // legal_b
        (const float*)d_in[15],  // legal_g
        (const float*)d_in[16],  // legal_beta
        (const float*)d_in[17],  // game_W
        (const float*)d_in[18],  // game_b
        (const float*)d_in[19],  // game_g
        (const float*)d_in[20],  // game_beta
        (const float*)d_in[21],  // ctx_W
        (const float*)d_in[22],  // ctx_b
        (const float*)d_in[23],  // ctx_g
        (const float*)d_in[24],  // ctx_beta
        (float*)d_out,
        tokens);
}